// round 1
// baseline (speedup 1.0000x reference)
#include <cuda_runtime.h>
#include <math.h>

// Model dims (fixed by the problem)
#define L_  8
#define H_  16
#define D_  1024
#define DH_ 64
#define FF_ 4096
#define V_  32000
#define S_  1024
#define B_  2
#define ROWS (B_*S_)   // 2048

// ---------------- scratch (static device globals; no allocation allowed) ----
__device__ float g_Wq [L_*D_*D_];
__device__ float g_Wk [L_*D_*D_];
__device__ float g_Wv [L_*D_*D_];
__device__ float g_h  [ROWS*D_];
__device__ float g_q  [ROWS*D_];
__device__ float g_k  [ROWS*D_];
__device__ float g_v  [ROWS*D_];
__device__ float g_att[ROWS*D_];
__device__ float g_tmp[ROWS*D_];
__device__ float g_ff [ROWS*FF_];

// ---------------- repack wq/wk/wv: [L,H,D,DH] -> [L, D, H*DH] row-major -----
__global__ void repack_kernel(const float* __restrict__ src, float* __restrict__ dst) {
    int i = blockIdx.x * blockDim.x + threadIdx.x;
    if (i >= L_*D_*D_) return;
    int l = i / (D_*D_);
    int r = i - l*(D_*D_);
    int d = r / D_;
    int n = r - d*D_;
    int h = n >> 6;      // /DH_
    int e = n & 63;
    dst[i] = src[(((size_t)l*H_ + h)*D_ + d)*DH_ + e];
}

// ---------------- embedding: h = tok_emb[x] + pos_emb ----------------------
__global__ void embed_kernel(const int* __restrict__ x, const float* __restrict__ tok,
                             const float* __restrict__ pos, float* __restrict__ out) {
    int i = blockIdx.x * blockDim.x + threadIdx.x;
    if (i >= ROWS*D_) return;
    int bs = i / D_;
    int d  = i - bs*D_;
    int s  = bs & (S_-1);
    int t  = x[bs];
    out[i] = tok[(size_t)t*D_ + d] + pos[(size_t)s*D_ + d];
}

// ---------------- generic fp32 GEMM:  C = A[MxK] @ B[KxN] + bias (opt relu) -
// 128x128 tile, BK=16, 256 threads, 8x8 micro-tile. All dims divide evenly.
#define BM 128
#define BN 128
#define BK 16

template<bool RELU>
__global__ __launch_bounds__(256, 2)
void gemm_kernel(const float* __restrict__ A, const float* __restrict__ B,
                 const float* __restrict__ bias, float* __restrict__ C,
                 int M, int N, int K) {
    __shared__ float As[BK][BM];
    __shared__ float Bs[BK][BN];

    const int tid  = threadIdx.x;
    const int tcol = tid & 15;   // 0..15 over N
    const int trow = tid >> 4;   // 0..15 over M
    const int bx = blockIdx.x;
    const int by = blockIdx.y;

    const float* Ablk = A + (size_t)by * BM * K;
    const float* Bblk = B + (size_t)bx * BN;

    float acc[8][8];
#pragma unroll
    for (int i = 0; i < 8; i++)
#pragma unroll
        for (int j = 0; j < 8; j++) acc[i][j] = 0.f;

    for (int k0 = 0; k0 < K; k0 += BK) {
        // A tile: 128 rows x 16 cols = 512 float4 loads; store transposed.
#pragma unroll
        for (int i = 0; i < 2; i++) {
            int idx = tid + i*256;           // 0..511
            int row = idx >> 2;
            int col = (idx & 3) << 2;
            float4 a = *(const float4*)(Ablk + (size_t)row*K + k0 + col);
            As[col+0][row] = a.x; As[col+1][row] = a.y;
            As[col+2][row] = a.z; As[col+3][row] = a.w;
        }
        // B tile: 16 rows x 128 cols, row-major, direct float4 copies.
#pragma unroll
        for (int i = 0; i < 2; i++) {
            int idx = tid + i*256;
            int row = idx >> 5;
            int col = (idx & 31) << 2;
            *(float4*)&Bs[row][col] = *(const float4*)(Bblk + (size_t)(k0+row)*N + col);
        }
        __syncthreads();

#pragma unroll
        for (int k = 0; k < BK; k++) {
            float4 a0 = *(float4*)&As[k][trow*8];
            float4 a1 = *(float4*)&As[k][trow*8+4];
            float4 b0 = *(float4*)&Bs[k][tcol*8];
            float4 b1 = *(float4*)&Bs[k][tcol*8+4];
            float ar[8] = {a0.x,a0.y,a0.z,a0.w,a1.x,a1.y,a1.z,a1.w};
            float br[8] = {b0.x,b0.y,b0.z,b0.w,b1.x,b1.y,b1.z,b1.w};
#pragma unroll
            for (int i = 0; i < 8; i++)
#pragma unroll
                for (int j = 0; j < 8; j++) acc[i][j] += ar[i]*br[j];
        }
        __syncthreads();
    }

    // epilogue: bias (+relu), vectorized store
    const int cbase = bx*BN + tcol*8;
    float bi[8];
#pragma unroll
    for (int j = 0; j < 8; j++) bi[j] = bias[cbase + j];
#pragma unroll
    for (int i = 0; i < 8; i++) {
        int row = by*BM + trow*8 + i;
        float* Crow = C + (size_t)row*N + cbase;
        float4 v0, v1;
        float vtmp[8];
#pragma unroll
        for (int j = 0; j < 8; j++) {
            float t = acc[i][j] + bi[j];
            if (RELU) t = fmaxf(t, 0.f);
            vtmp[j] = t;
        }
        v0 = make_float4(vtmp[0],vtmp[1],vtmp[2],vtmp[3]);
        v1 = make_float4(vtmp[4],vtmp[5],vtmp[6],vtmp[7]);
        *(float4*)Crow     = v0;
        *(float4*)(Crow+4) = v1;
    }
}

// ---------------- causal flash attention (fp32) -----------------------------
// grid: (S/128, B*H). 128 threads; 1 thread = 1 query row. K/V tiled 32 keys.
__global__ __launch_bounds__(128, 2)
void attn_kernel(const float* __restrict__ q, const float* __restrict__ k,
                 const float* __restrict__ v, float* __restrict__ o) {
    const int tid = threadIdx.x;                  // 0..127
    const int s   = blockIdx.x * 128 + tid;       // query position
    const int bh  = blockIdx.y;
    const int b   = bh >> 4;                      // /H_
    const int h   = bh & 15;
    const float scale = 0.125f;                   // 1/sqrt(64)

    __shared__ float ks[32][64];
    __shared__ float vs[32][64];

    const float* qrow = q + ((size_t)(b*S_ + s))*D_ + h*DH_;
    float qr[64], acc[64];
#pragma unroll
    for (int d = 0; d < 64; d++) { qr[d] = qrow[d]; acc[d] = 0.f; }
    float m = -1e30f, lsum = 0.f;

    const int kt_max = (blockIdx.x*128 + 127) >> 5;   // inclusive
    for (int kt = 0; kt <= kt_max; kt++) {
        const float* kbase = k + ((size_t)(b*S_ + kt*32))*D_ + h*DH_;
        const float* vbase = v + ((size_t)(b*S_ + kt*32))*D_ + h*DH_;
#pragma unroll
        for (int i = 0; i < 4; i++) {
            int idx = tid + i*128;         // 0..511 float4 slots (32x16)
            int r = idx >> 4;
            int c = (idx & 15) << 2;
            *(float4*)&ks[r][c] = *(const float4*)(kbase + (size_t)r*D_ + c);
            *(float4*)&vs[r][c] = *(const float4*)(vbase + (size_t)r*D_ + c);
        }
        __syncthreads();

        float sc[32];
        float tmax = -1e30f;
#pragma unroll
        for (int t = 0; t < 32; t++) {
            float dot = 0.f;
#pragma unroll
            for (int d = 0; d < 64; d++) dot += qr[d]*ks[t][d];
            int kk = kt*32 + t;
            sc[t] = (kk <= s) ? dot*scale : -1e30f;
            tmax = fmaxf(tmax, sc[t]);
        }
        float mnew = fmaxf(m, tmax);
        float corr = __expf(m - mnew);
        lsum *= corr;
#pragma unroll
        for (int d = 0; d < 64; d++) acc[d] *= corr;
#pragma unroll
        for (int t = 0; t < 32; t++) {
            float p = __expf(sc[t] - mnew);
            lsum += p;
#pragma unroll
            for (int d = 0; d < 64; d++) acc[d] += p * vs[t][d];
        }
        m = mnew;
        __syncthreads();
    }
    float inv = 1.f / lsum;
    float* orow = o + ((size_t)(b*S_ + s))*D_ + h*DH_;
#pragma unroll
    for (int d = 0; d < 64; d++) orow[d] = acc[d]*inv;
}

// ---------------- residual add + LayerNorm (in-place into hres) -------------
__global__ void add_ln_kernel(const float* __restrict__ a, float* __restrict__ hres,
                              const float* __restrict__ g, const float* __restrict__ bta) {
    const int row = blockIdx.x;
    const int tid = threadIdx.x;   // 256
    __shared__ float xs[D_];
    __shared__ float rbuf[2][8];
    __shared__ float stats[2];

    float s1 = 0.f, s2 = 0.f;
    for (int i = tid; i < D_; i += 256) {
        float x = a[(size_t)row*D_+i] + hres[(size_t)row*D_+i];
        xs[i] = x; s1 += x; s2 += x*x;
    }
#pragma unroll
    for (int off = 16; off; off >>= 1) {
        s1 += __shfl_down_sync(0xffffffffu, s1, off);
        s2 += __shfl_down_sync(0xffffffffu, s2, off);
    }
    if ((tid & 31) == 0) { rbuf[0][tid>>5] = s1; rbuf[1][tid>>5] = s2; }
    __syncthreads();
    if (tid == 0) {
        float t1 = 0.f, t2 = 0.f;
        for (int w = 0; w < 8; w++) { t1 += rbuf[0][w]; t2 += rbuf[1][w]; }
        float mu  = t1 * (1.f/D_);
        float var = t2 * (1.f/D_) - mu*mu;
        stats[0] = mu; stats[1] = rsqrtf(var + 1e-5f);
    }
    __syncthreads();
    float mu = stats[0], rstd = stats[1];
    for (int i = tid; i < D_; i += 256)
        hres[(size_t)row*D_+i] = (xs[i]-mu)*rstd*g[i] + bta[i];
}

// ---------------- log_softmax over V, in-place -------------------------------
__global__ void logsoftmax_kernel(float* __restrict__ out) {
    const int row = blockIdx.x;
    const int tid = threadIdx.x;   // 256
    float* p = out + (size_t)row * V_;
    __shared__ float rbuf[8];
    __shared__ float smax, slse;

    float lmax = -1e30f;
    for (int i = tid; i < V_; i += 256) lmax = fmaxf(lmax, p[i]);
#pragma unroll
    for (int off = 16; off; off >>= 1)
        lmax = fmaxf(lmax, __shfl_down_sync(0xffffffffu, lmax, off));
    if ((tid & 31) == 0) rbuf[tid>>5] = lmax;
    __syncthreads();
    if (tid == 0) {
        float mtot = -1e30f;
        for (int w = 0; w < 8; w++) mtot = fmaxf(mtot, rbuf[w]);
        smax = mtot;
    }
    __syncthreads();
    float mx = smax;

    float lsum = 0.f;
    for (int i = tid; i < V_; i += 256) lsum += __expf(p[i] - mx);
#pragma unroll
    for (int off = 16; off; off >>= 1)
        lsum += __shfl_down_sync(0xffffffffu, lsum, off);
    if ((tid & 31) == 0) rbuf[tid>>5] = lsum;
    __syncthreads();
    if (tid == 0) {
        float stot = 0.f;
        for (int w = 0; w < 8; w++) stot += rbuf[w];
        slse = logf(stot) + mx;
    }
    __syncthreads();
    float lse = slse;
    for (int i = tid; i < V_; i += 256) p[i] = p[i] - lse;
}

// ---------------- host-side helpers ------------------------------------------
static inline void gemm(const float* A, const float* B, const float* bias, float* C,
                        int M, int N, int K, bool relu) {
    dim3 g(N/BN, M/BM);
    if (relu) gemm_kernel<true ><<<g, 256>>>(A, B, bias, C, M, N, K);
    else      gemm_kernel<false><<<g, 256>>>(A, B, bias, C, M, N, K);
}

extern "C" void kernel_launch(void* const* d_in, const int* in_sizes, int n_in,
                              void* d_out, int out_size) {
    const int*   x    = (const int*)  d_in[0];
    const float* tok  = (const float*)d_in[1];
    const float* pos  = (const float*)d_in[2];
    const float* wq   = (const float*)d_in[3];
    const float* bq   = (const float*)d_in[4];
    const float* wk   = (const float*)d_in[5];
    const float* bk   = (const float*)d_in[6];
    const float* wv   = (const float*)d_in[7];
    const float* bv   = (const float*)d_in[8];
    const float* wo   = (const float*)d_in[9];
    const float* bo   = (const float*)d_in[10];
    const float* ln1g = (const float*)d_in[11];
    const float* ln1b = (const float*)d_in[12];
    const float* w1   = (const float*)d_in[13];
    const float* b1   = (const float*)d_in[14];
    const float* w2   = (const float*)d_in[15];
    const float* b2   = (const float*)d_in[16];
    const float* ln2g = (const float*)d_in[17];
    const float* ln2b = (const float*)d_in[18];
    const float* wout = (const float*)d_in[19];
    const float* bout = (const float*)d_in[20];
    float* out = (float*)d_out;

    float *Wq, *Wk, *Wv, *h, *q, *k, *v, *att, *tmp, *ff;
    cudaGetSymbolAddress((void**)&Wq,  g_Wq);
    cudaGetSymbolAddress((void**)&Wk,  g_Wk);
    cudaGetSymbolAddress((void**)&Wv,  g_Wv);
    cudaGetSymbolAddress((void**)&h,   g_h);
    cudaGetSymbolAddress((void**)&q,   g_q);
    cudaGetSymbolAddress((void**)&k,   g_k);
    cudaGetSymbolAddress((void**)&v,   g_v);
    cudaGetSymbolAddress((void**)&att, g_att);
    cudaGetSymbolAddress((void**)&tmp, g_tmp);
    cudaGetSymbolAddress((void**)&ff,  g_ff);

    // repack per-head qkv weights into row-major [D, D]
    {
        int n = L_*D_*D_;
        int blocks = (n + 255) / 256;
        repack_kernel<<<blocks, 256>>>(wq, Wq);
        repack_kernel<<<blocks, 256>>>(wk, Wk);
        repack_kernel<<<blocks, 256>>>(wv, Wv);
    }

    // embedding
    {
        int n = ROWS*D_;
        embed_kernel<<<(n + 255)/256, 256>>>(x, tok, pos, h);
    }

    for (int l = 0; l < L_; l++) {
        const float* Wql = Wq + (size_t)l*D_*D_;
        const float* Wkl = Wk + (size_t)l*D_*D_;
        const float* Wvl = Wv + (size_t)l*D_*D_;

        gemm(h, Wql, bq + (size_t)l*D_, q, ROWS, D_, D_, false);
        gemm(h, Wkl, bk + (size_t)l*D_, k, ROWS, D_, D_, false);
        gemm(h, Wvl, bv + (size_t)l*D_, v, ROWS, D_, D_, false);

        dim3 ag(S_/128, B_*H_);
        attn_kernel<<<ag, 128>>>(q, k, v, att);

        gemm(att, wo + (size_t)l*D_*D_, bo + (size_t)l*D_, tmp, ROWS, D_, D_, false);
        add_ln_kernel<<<ROWS, 256>>>(tmp, h, ln1g + (size_t)l*D_, ln1b + (size_t)l*D_);

        gemm(h,  w1 + (size_t)l*D_*FF_, b1 + (size_t)l*FF_, ff,  ROWS, FF_, D_, true);
        gemm(ff, w2 + (size_t)l*FF_*D_, b2 + (size_t)l*D_,  tmp, ROWS, D_,  FF_, false);
        add_ln_kernel<<<ROWS, 256>>>(tmp, h, ln2g + (size_t)l*D_, ln2b + (size_t)l*D_);
    }

    // final vocab projection + log_softmax (in-place on d_out)
    gemm(h, wout, bout, out, ROWS, V_, D_, false);
    logsoftmax_kernel<<<ROWS, 256>>>(out);
}

// round 4
// speedup vs baseline: 2.3817x; 2.3817x over previous
#include <cuda_runtime.h>
#include <math.h>
#include <stdint.h>

// Model dims (fixed by the problem)
#define L_  8
#define H_  16
#define D_  1024
#define DH_ 64
#define FF_ 4096
#define V_  32000
#define S_  1024
#define B_  2
#define ROWS (B_*S_)   // 2048

// ---------------- scratch (static device globals; no allocation allowed) ----
__device__ float g_Wq [L_*D_*D_];
__device__ float g_Wk [L_*D_*D_];
__device__ float g_Wv [L_*D_*D_];
__device__ float g_h  [ROWS*D_];
__device__ float g_q  [ROWS*D_];
__device__ float g_k  [ROWS*D_];
__device__ float g_v  [ROWS*D_];
__device__ float g_att[ROWS*D_];
__device__ float g_tmp[ROWS*D_];
__device__ float g_ff [ROWS*FF_];

// ---------------- repack wq/wk/wv: [L,H,D,DH] -> [L, D, H*DH] row-major -----
__global__ void repack_kernel(const float* __restrict__ src, float* __restrict__ dst) {
    int i = blockIdx.x * blockDim.x + threadIdx.x;
    if (i >= L_*D_*D_) return;
    int l = i / (D_*D_);
    int r = i - l*(D_*D_);
    int d = r / D_;
    int n = r - d*D_;
    int h = n >> 6;      // /DH_
    int e = n & 63;
    dst[i] = src[(((size_t)l*H_ + h)*D_ + d)*DH_ + e];
}

// ---------------- embedding: h = tok_emb[x] + pos_emb ----------------------
__global__ void embed_kernel(const int* __restrict__ x, const float* __restrict__ tok,
                             const float* __restrict__ pos, float* __restrict__ out) {
    int i = blockIdx.x * blockDim.x + threadIdx.x;
    if (i >= ROWS*D_) return;
    int bs = i / D_;
    int d  = i - bs*D_;
    int s  = bs & (S_-1);
    int t  = x[bs];
    out[i] = tok[(size_t)t*D_ + d] + pos[(size_t)s*D_ + d];
}

// ---------------- tf32 tensor-core GEMM:  C = A[MxK] @ B[KxN] + bias --------
// 128x128 CTA tile, BK=16, 256 threads (8 warps, each 32x64),
// mma.sync.m16n8k8 tf32, cp.async double-buffered SMEM.
#define BM 128
#define BN 128
#define BK 16

#define CP16(dst_u32, src_ptr) \
    asm volatile("cp.async.cg.shared.global [%0], [%1], 16;\n" :: "r"(dst_u32), "l"(src_ptr))

__device__ __forceinline__ void mma_tf32(float c[4], const uint32_t a[4], const uint32_t b[2]) {
    asm volatile(
        "mma.sync.aligned.m16n8k8.row.col.f32.tf32.tf32.f32 "
        "{%0,%1,%2,%3}, {%4,%5,%6,%7}, {%8,%9}, {%0,%1,%2,%3};\n"
        : "+f"(c[0]), "+f"(c[1]), "+f"(c[2]), "+f"(c[3])
        : "r"(a[0]), "r"(a[1]), "r"(a[2]), "r"(a[3]), "r"(b[0]), "r"(b[1]));
}

template<bool RELU>
__global__ __launch_bounds__(256)
void gemm_tc_kernel(const float* __restrict__ A, const float* __restrict__ B,
                    const float* __restrict__ bias, float* __restrict__ C,
                    int M, int N, int K) {
    // As: row-major [m][k], padded to 20 floats/row  -> conflict-free A-frag LDS
    // Bs: [k][n], padded to 136 floats/row           -> conflict-free B-frag LDS
    __shared__ __align__(16) float As[2][BM][20];
    __shared__ __align__(16) float Bs[2][BK][136];

    const int tid   = threadIdx.x;
    const int warp  = tid >> 5;
    const int lane  = tid & 31;
    const int warpM = warp >> 1;        // 0..3  -> 32-row slab
    const int warpN = warp & 1;         // 0..1  -> 64-col slab
    const int gid   = lane >> 2;        // 0..7
    const int tig   = lane & 3;         // 0..3

    const int bm = blockIdx.y * BM;
    const int bn = blockIdx.x * BN;

    float acc[2][8][4];
#pragma unroll
    for (int mt = 0; mt < 2; mt++)
#pragma unroll
        for (int nt = 0; nt < 8; nt++)
#pragma unroll
            for (int i = 0; i < 4; i++) acc[mt][nt][i] = 0.f;

    const int KT = K / BK;

    // --- async tile copy (A: 512 f4, B: 512 f4; 2 each per thread) ---
    auto copy_tile = [&](int k0, int buf) {
#pragma unroll
        for (int i = 0; i < 2; i++) {
            int idx = tid + i*256;
            int row = idx >> 2;
            int kc  = (idx & 3) << 2;
            const float* src = A + (size_t)(bm + row)*K + k0 + kc;
            uint32_t dst = (uint32_t)__cvta_generic_to_shared(&As[buf][row][kc]);
            CP16(dst, src);
        }
#pragma unroll
        for (int i = 0; i < 2; i++) {
            int idx = tid + i*256;
            int row = idx >> 5;
            int nc  = (idx & 31) << 2;
            const float* src = B + (size_t)(k0 + row)*N + bn + nc;
            uint32_t dst = (uint32_t)__cvta_generic_to_shared(&Bs[buf][row][nc]);
            CP16(dst, src);
        }
        asm volatile("cp.async.commit_group;\n");
    };

    copy_tile(0, 0);

    for (int it = 0; it < KT; it++) {
        const int buf = it & 1;
        if (it + 1 < KT) {
            copy_tile((it + 1) * BK, buf ^ 1);
            asm volatile("cp.async.wait_group 1;\n");
        } else {
            asm volatile("cp.async.wait_group 0;\n");
        }
        __syncthreads();

#pragma unroll
        for (int kk = 0; kk < 2; kk++) {
            const int kb = kk * 8;
            uint32_t af[2][4];
#pragma unroll
            for (int mt = 0; mt < 2; mt++) {
                int r0 = warpM*32 + mt*16 + gid;
                af[mt][0] = __float_as_uint(As[buf][r0    ][kb + tig    ]);
                af[mt][1] = __float_as_uint(As[buf][r0 + 8][kb + tig    ]);
                af[mt][2] = __float_as_uint(As[buf][r0    ][kb + tig + 4]);
                af[mt][3] = __float_as_uint(As[buf][r0 + 8][kb + tig + 4]);
            }
#pragma unroll
            for (int nt = 0; nt < 8; nt++) {
                int c0 = warpN*64 + nt*8 + gid;
                uint32_t bf[2];
                bf[0] = __float_as_uint(Bs[buf][kb + tig    ][c0]);
                bf[1] = __float_as_uint(Bs[buf][kb + tig + 4][c0]);
                mma_tf32(acc[0][nt], af[0], bf);
                mma_tf32(acc[1][nt], af[1], bf);
            }
        }
        __syncthreads();
    }

    // --- epilogue: bias (+relu), float2 stores ---
#pragma unroll
    for (int mt = 0; mt < 2; mt++) {
#pragma unroll
        for (int nt = 0; nt < 8; nt++) {
            int row = bm + warpM*32 + mt*16 + gid;
            int col = bn + warpN*64 + nt*8 + tig*2;
            float b0 = bias[col], b1 = bias[col + 1];
            float v0 = acc[mt][nt][0] + b0;
            float v1 = acc[mt][nt][1] + b1;
            float v2 = acc[mt][nt][2] + b0;
            float v3 = acc[mt][nt][3] + b1;
            if (RELU) {
                v0 = fmaxf(v0, 0.f); v1 = fmaxf(v1, 0.f);
                v2 = fmaxf(v2, 0.f); v3 = fmaxf(v3, 0.f);
            }
            *(float2*)(C + (size_t)row*N + col)       = make_float2(v0, v1);
            *(float2*)(C + (size_t)(row + 8)*N + col) = make_float2(v2, v3);
        }
    }
}

// ---------------- causal flash attention (fp32) -----------------------------
// grid: (S/128, B*H). 128 threads; 1 thread = 1 query row. K/V tiled 32 keys.
__global__ __launch_bounds__(128, 2)
void attn_kernel(const float* __restrict__ q, const float* __restrict__ k,
                 const float* __restrict__ v, float* __restrict__ o) {
    const int tid = threadIdx.x;                  // 0..127
    const int s   = blockIdx.x * 128 + tid;       // query position
    const int bh  = blockIdx.y;
    const int b   = bh >> 4;                      // /H_
    const int h   = bh & 15;
    const float scale = 0.125f;                   // 1/sqrt(64)

    __shared__ float ks[32][64];
    __shared__ float vs[32][64];

    const float* qrow = q + ((size_t)(b*S_ + s))*D_ + h*DH_;
    float qr[64], acc[64];
#pragma unroll
    for (int d = 0; d < 64; d++) { qr[d] = qrow[d]; acc[d] = 0.f; }
    float m = -1e30f, lsum = 0.f;

    const int kt_max = (blockIdx.x*128 + 127) >> 5;   // inclusive
    for (int kt = 0; kt <= kt_max; kt++) {
        const float* kbase = k + ((size_t)(b*S_ + kt*32))*D_ + h*DH_;
        const float* vbase = v + ((size_t)(b*S_ + kt*32))*D_ + h*DH_;
#pragma unroll
        for (int i = 0; i < 4; i++) {
            int idx = tid + i*128;         // 0..511 float4 slots (32x16)
            int r = idx >> 4;
            int c = (idx & 15) << 2;
            *(float4*)&ks[r][c] = *(const float4*)(kbase + (size_t)r*D_ + c);
            *(float4*)&vs[r][c] = *(const float4*)(vbase + (size_t)r*D_ + c);
        }
        __syncthreads();

        float sc[32];
        float tmax = -1e30f;
#pragma unroll
        for (int t = 0; t < 32; t++) {
            float dot = 0.f;
#pragma unroll
            for (int d = 0; d < 64; d++) dot += qr[d]*ks[t][d];
            int kk = kt*32 + t;
            sc[t] = (kk <= s) ? dot*scale : -1e30f;
            tmax = fmaxf(tmax, sc[t]);
        }
        float mnew = fmaxf(m, tmax);
        float corr = __expf(m - mnew);
        lsum *= corr;
#pragma unroll
        for (int d = 0; d < 64; d++) acc[d] *= corr;
#pragma unroll
        for (int t = 0; t < 32; t++) {
            float p = __expf(sc[t] - mnew);
            lsum += p;
#pragma unroll
            for (int d = 0; d < 64; d++) acc[d] += p * vs[t][d];
        }
        m = mnew;
        __syncthreads();
    }
    float inv = 1.f / lsum;
    float* orow = o + ((size_t)(b*S_ + s))*D_ + h*DH_;
#pragma unroll
    for (int d = 0; d < 64; d++) orow[d] = acc[d]*inv;
}

// ---------------- residual add + LayerNorm (in-place into hres) -------------
__global__ void add_ln_kernel(const float* __restrict__ a, float* __restrict__ hres,
                              const float* __restrict__ g, const float* __restrict__ bta) {
    const int row = blockIdx.x;
    const int tid = threadIdx.x;   // 256
    __shared__ float xs[D_];
    __shared__ float rbuf[2][8];
    __shared__ float stats[2];

    float s1 = 0.f, s2 = 0.f;
    for (int i = tid; i < D_; i += 256) {
        float x = a[(size_t)row*D_+i] + hres[(size_t)row*D_+i];
        xs[i] = x; s1 += x; s2 += x*x;
    }
#pragma unroll
    for (int off = 16; off; off >>= 1) {
        s1 += __shfl_down_sync(0xffffffffu, s1, off);
        s2 += __shfl_down_sync(0xffffffffu, s2, off);
    }
    if ((tid & 31) == 0) { rbuf[0][tid>>5] = s1; rbuf[1][tid>>5] = s2; }
    __syncthreads();
    if (tid == 0) {
        float t1 = 0.f, t2 = 0.f;
        for (int w = 0; w < 8; w++) { t1 += rbuf[0][w]; t2 += rbuf[1][w]; }
        float mu  = t1 * (1.f/D_);
        float var = t2 * (1.f/D_) - mu*mu;
        stats[0] = mu; stats[1] = rsqrtf(var + 1e-5f);
    }
    __syncthreads();
    float mu = stats[0], rstd = stats[1];
    for (int i = tid; i < D_; i += 256)
        hres[(size_t)row*D_+i] = (xs[i]-mu)*rstd*g[i] + bta[i];
}

// ---------------- log_softmax over V, in-place -------------------------------
__global__ void logsoftmax_kernel(float* __restrict__ out) {
    const int row = blockIdx.x;
    const int tid = threadIdx.x;   // 256
    float* p = out + (size_t)row * V_;
    __shared__ float rbuf[8];
    __shared__ float smax, slse;

    float lmax = -1e30f;
    for (int i = tid; i < V_; i += 256) lmax = fmaxf(lmax, p[i]);
#pragma unroll
    for (int off = 16; off; off >>= 1)
        lmax = fmaxf(lmax, __shfl_down_sync(0xffffffffu, lmax, off));
    if ((tid & 31) == 0) rbuf[tid>>5] = lmax;
    __syncthreads();
    if (tid == 0) {
        float mtot = -1e30f;
        for (int w = 0; w < 8; w++) mtot = fmaxf(mtot, rbuf[w]);
        smax = mtot;
    }
    __syncthreads();
    float mx = smax;

    float lsum = 0.f;
    for (int i = tid; i < V_; i += 256) lsum += __expf(p[i] - mx);
#pragma unroll
    for (int off = 16; off; off >>= 1)
        lsum += __shfl_down_sync(0xffffffffu, lsum, off);
    if ((tid & 31) == 0) rbuf[tid>>5] = lsum;
    __syncthreads();
    if (tid == 0) {
        float stot = 0.f;
        for (int w = 0; w < 8; w++) stot += rbuf[w];
        slse = logf(stot) + mx;
    }
    __syncthreads();
    float lse = slse;
    for (int i = tid; i < V_; i += 256) p[i] = p[i] - lse;
}

// ---------------- host-side helpers ------------------------------------------
static inline void gemm(const float* A, const float* B, const float* bias, float* C,
                        int M, int N, int K, bool relu) {
    dim3 g(N/BN, M/BM);
    if (relu) gemm_tc_kernel<true ><<<g, 256>>>(A, B, bias, C, M, N, K);
    else      gemm_tc_kernel<false><<<g, 256>>>(A, B, bias, C, M, N, K);
}

extern "C" void kernel_launch(void* const* d_in, const int* in_sizes, int n_in,
                              void* d_out, int out_size) {
    const int*   x    = (const int*)  d_in[0];
    const float* tok  = (const float*)d_in[1];
    const float* pos  = (const float*)d_in[2];
    const float* wq   = (const float*)d_in[3];
    const float* bq   = (const float*)d_in[4];
    const float* wk   = (const float*)d_in[5];
    const float* bk   = (const float*)d_in[6];
    const float* wv   = (const float*)d_in[7];
    const float* bv   = (const float*)d_in[8];
    const float* wo   = (const float*)d_in[9];
    const float* bo   = (const float*)d_in[10];
    const float* ln1g = (const float*)d_in[11];
    const float* ln1b = (const float*)d_in[12];
    const float* w1   = (const float*)d_in[13];
    const float* b1   = (const float*)d_in[14];
    const float* w2   = (const float*)d_in[15];
    const float* b2   = (const float*)d_in[16];
    const float* ln2g = (const float*)d_in[17];
    const float* ln2b = (const float*)d_in[18];
    const float* wout = (const float*)d_in[19];
    const float* bout = (const float*)d_in[20];
    float* out = (float*)d_out;

    float *Wq, *Wk, *Wv, *h, *q, *k, *v, *att, *tmp, *ff;
    cudaGetSymbolAddress((void**)&Wq,  g_Wq);
    cudaGetSymbolAddress((void**)&Wk,  g_Wk);
    cudaGetSymbolAddress((void**)&Wv,  g_Wv);
    cudaGetSymbolAddress((void**)&h,   g_h);
    cudaGetSymbolAddress((void**)&q,   g_q);
    cudaGetSymbolAddress((void**)&k,   g_k);
    cudaGetSymbolAddress((void**)&v,   g_v);
    cudaGetSymbolAddress((void**)&att, g_att);
    cudaGetSymbolAddress((void**)&tmp, g_tmp);
    cudaGetSymbolAddress((void**)&ff,  g_ff);

    // repack per-head qkv weights into row-major [D, D]
    {
        int n = L_*D_*D_;
        int blocks = (n + 255) / 256;
        repack_kernel<<<blocks, 256>>>(wq, Wq);
        repack_kernel<<<blocks, 256>>>(wk, Wk);
        repack_kernel<<<blocks, 256>>>(wv, Wv);
    }

    // embedding
    {
        int n = ROWS*D_;
        embed_kernel<<<(n + 255)/256, 256>>>(x, tok, pos, h);
    }

    for (int l = 0; l < L_; l++) {
        const float* Wql = Wq + (size_t)l*D_*D_;
        const float* Wkl = Wk + (size_t)l*D_*D_;
        const float* Wvl = Wv + (size_t)l*D_*D_;

        gemm(h, Wql, bq + (size_t)l*D_, q, ROWS, D_, D_, false);
        gemm(h, Wkl, bk + (size_t)l*D_, k, ROWS, D_, D_, false);
        gemm(h, Wvl, bv + (size_t)l*D_, v, ROWS, D_, D_, false);

        dim3 ag(S_/128, B_*H_);
        attn_kernel<<<ag, 128>>>(q, k, v, att);

        gemm(att, wo + (size_t)l*D_*D_, bo + (size_t)l*D_, tmp, ROWS, D_, D_, false);
        add_ln_kernel<<<ROWS, 256>>>(tmp, h, ln1g + (size_t)l*D_, ln1b + (size_t)l*D_);

        gemm(h,  w1 + (size_t)l*D_*FF_, b1 + (size_t)l*FF_, ff,  ROWS, FF_, D_, true);
        gemm(ff, w2 + (size_t)l*FF_*D_, b2 + (size_t)l*D_,  tmp, ROWS, D_,  FF_, false);
        add_ln_kernel<<<ROWS, 256>>>(tmp, h, ln2g + (size_t)l*D_, ln2b + (size_t)l*D_);
    }

    // final vocab projection + log_softmax (in-place on d_out)
    gemm(h, wout, bout, out, ROWS, V_, D_, false);
    logsoftmax_kernel<<<ROWS, 256>>>(out);
}